// round 2
// baseline (speedup 1.0000x reference)
#include <cuda_runtime.h>
#include <cuda_bf16.h>
#include <cstdint>

#define N_NODES 80000
#define N_EDGES 1280000
#define HID     64

// ---------------- device scratch (no allocations allowed) ----------------
__device__ int   d_cnt[N_NODES];
__device__ int   d_rowptr[N_NODES + 1];
__device__ int   d_cursor[N_NODES];
__device__ int   d_bsum[128];
__device__ int   d_boff[128];
__device__ int   d_col[N_EDGES];
__device__ float d_dinv[N_NODES];
__device__ float d_g[N_NODES * HID];   // GEMM output, packed pair layout
__device__ float d_h[N_NODES * HID];   // layer output, packed pair layout
__device__ float d_pooled[64 * 64];

// Packed pair layout: float2 at index v*32+p holds (channel p, channel p+32).

// ---------------- threefry-2x32 (exact JAX semantics) ----------------
__device__ __forceinline__ uint2 threefry_dev(unsigned k0, unsigned k1,
                                              unsigned c0, unsigned c1) {
    unsigned ks2 = k0 ^ k1 ^ 0x1BD11BDAu;
    unsigned x0 = c0 + k0, x1 = c1 + k1;
#define TF_RND(r) { x0 += x1; x1 = __funnelshift_l(x1, x1, (r)); x1 ^= x0; }
    TF_RND(13) TF_RND(15) TF_RND(26) TF_RND(6)   x0 += k1;  x1 += ks2 + 1u;
    TF_RND(17) TF_RND(29) TF_RND(16) TF_RND(24)  x0 += ks2; x1 += k0 + 2u;
    TF_RND(13) TF_RND(15) TF_RND(26) TF_RND(6)   x0 += k0;  x1 += k1 + 3u;
    TF_RND(17) TF_RND(29) TF_RND(16) TF_RND(24)  x0 += k1;  x1 += ks2 + 4u;
    TF_RND(13) TF_RND(15) TF_RND(26) TF_RND(6)   x0 += ks2; x1 += k0 + 5u;
#undef TF_RND
    return make_uint2(x0, x1);
}

// Partitionable threefry random_bits(32): per flat element i,
// (b1,b2) = threefry(key, (0, i)); bits = b1 ^ b2.
__device__ __forceinline__ bool keep_elem(unsigned k0, unsigned k1, unsigned idx) {
    uint2 r = threefry_dev(k0, k1, 0u, idx);
    unsigned bits = r.x ^ r.y;
    // jax.random.uniform: u = bitcast((bits>>9)|0x3f800000, f32) - 1.0; keep = u < 0.7
    float u = __uint_as_float((bits >> 9) | 0x3f800000u) - 1.0f;
    return u < 0.7f;
}

// ---------------- CSR build ----------------
__global__ void k_zero_cnt() {
    int i = blockIdx.x * 256 + threadIdx.x;
    if (i < N_NODES) d_cnt[i] = 0;
}
__global__ void k_hist(const int* __restrict__ ei) {
    int e = blockIdx.x * 256 + threadIdx.x;
    if (e < N_EDGES) atomicAdd(&d_cnt[ei[N_EDGES + e]], 1);
}
__global__ void k_scan1() {
    __shared__ int s[1024];
    int tid = threadIdx.x;
    int i = blockIdx.x * 1024 + tid;
    int v = (i < N_NODES) ? d_cnt[i] : 0;
    s[tid] = v;
    __syncthreads();
    for (int off = 1; off < 1024; off <<= 1) {
        int t = (tid >= off) ? s[tid - off] : 0;
        __syncthreads();
        s[tid] += t;
        __syncthreads();
    }
    if (i < N_NODES) d_rowptr[i] = s[tid] - v;   // exclusive within block
    if (tid == 1023) d_bsum[blockIdx.x] = s[1023];
}
__global__ void k_scan2(int nblocks) {
    if (threadIdx.x == 0) {
        int run = 0;
        for (int b = 0; b < nblocks; b++) { d_boff[b] = run; run += d_bsum[b]; }
    }
}
__global__ void k_scan3() {
    int i = blockIdx.x * 256 + threadIdx.x;
    if (i < N_NODES) {
        int r = d_rowptr[i] + d_boff[i >> 10];
        d_rowptr[i] = r;
        d_cursor[i] = r;
        d_dinv[i] = rsqrtf((float)d_cnt[i] + 1.0f);
    }
    if (i == 0) d_rowptr[N_NODES] = N_EDGES;
}
__global__ void k_scatter(const int* __restrict__ ei) {
    int e = blockIdx.x * 256 + threadIdx.x;
    if (e < N_EDGES) {
        int dst = ei[N_EDGES + e];
        int pos = atomicAdd(&d_cursor[dst], 1);
        d_col[pos] = ei[e];
    }
}

// ---------------- GEMM: g = (X @ W) * dinv, packed-pair output ----------------
// K = input width (128 or 64). PERM: input is d_h in packed layout -> permute W rows.
template <int K, bool PERM>
__global__ void k_gemm(const float* __restrict__ Xin, const float* __restrict__ W) {
    __shared__ float  Xs[64][68];
    __shared__ float2 Ws[64][32];
    const float* __restrict__ X = PERM ? (const float*)d_h : Xin;
    const int tid = threadIdx.x;
    const int rowBase = blockIdx.x * 64;
    const int tx = tid & 15, ty = tid >> 4;
    const int p0 = tx * 2, r0 = ty * 4;
    float2 acc[4][2] = {};

    for (int kb = 0; kb < K; kb += 64) {
        for (int idx = tid; idx < 64 * 64; idx += 256) {
            int row = idx >> 6, kk = idx & 63;
            int grow = rowBase + row;
            Xs[row][kk] = (grow < N_NODES) ? X[(size_t)grow * K + kb + kk] : 0.0f;
        }
        for (int idx = tid; idx < 64 * 32; idx += 256) {
            int kk = idx >> 5, p = idx & 31;
            int s = kb + kk;
            int krow = PERM ? ((s >> 1) + ((s & 1) << 5)) : s;
            Ws[kk][p] = make_float2(W[krow * 64 + p], W[krow * 64 + p + 32]);
        }
        __syncthreads();
#pragma unroll
        for (int kk = 0; kk < 64; ++kk) {
            float2 w0 = Ws[kk][p0];
            float2 w1 = Ws[kk][p0 + 1];
            float x0 = Xs[r0 + 0][kk], x1 = Xs[r0 + 1][kk];
            float x2 = Xs[r0 + 2][kk], x3 = Xs[r0 + 3][kk];
            acc[0][0].x = fmaf(x0, w0.x, acc[0][0].x); acc[0][0].y = fmaf(x0, w0.y, acc[0][0].y);
            acc[0][1].x = fmaf(x0, w1.x, acc[0][1].x); acc[0][1].y = fmaf(x0, w1.y, acc[0][1].y);
            acc[1][0].x = fmaf(x1, w0.x, acc[1][0].x); acc[1][0].y = fmaf(x1, w0.y, acc[1][0].y);
            acc[1][1].x = fmaf(x1, w1.x, acc[1][1].x); acc[1][1].y = fmaf(x1, w1.y, acc[1][1].y);
            acc[2][0].x = fmaf(x2, w0.x, acc[2][0].x); acc[2][0].y = fmaf(x2, w0.y, acc[2][0].y);
            acc[2][1].x = fmaf(x2, w1.x, acc[2][1].x); acc[2][1].y = fmaf(x2, w1.y, acc[2][1].y);
            acc[3][0].x = fmaf(x3, w0.x, acc[3][0].x); acc[3][0].y = fmaf(x3, w0.y, acc[3][0].y);
            acc[3][1].x = fmaf(x3, w1.x, acc[3][1].x); acc[3][1].y = fmaf(x3, w1.y, acc[3][1].y);
        }
        __syncthreads();
    }
#pragma unroll
    for (int i = 0; i < 4; i++) {
        int row = rowBase + r0 + i;
        if (row < N_NODES) {
            float di = d_dinv[row];
            float4 o = make_float4(acc[i][0].x * di, acc[i][0].y * di,
                                   acc[i][1].x * di, acc[i][1].y * di);
            *reinterpret_cast<float4*>(&d_g[(size_t)row * 64 + p0 * 2]) = o;
        }
    }
}

// ---------------- Aggregation + bias + ReLU + exact-JAX dropout ----------------
// One warp per node; lane handles channels (lane, lane+32) as one float2.
__global__ void k_agg(const float* __restrict__ bias, unsigned k0, unsigned k1) {
    int v = (blockIdx.x * blockDim.x + threadIdx.x) >> 5;
    int lane = threadIdx.x & 31;
    if (v >= N_NODES) return;
    const float2* __restrict__ g2 = reinterpret_cast<const float2*>(d_g);

    int beg = d_rowptr[v], end = d_rowptr[v + 1];
    float2 acc = g2[v * 32 + lane];           // self-loop term (g = h*dinv)
    int j = beg;
    for (; j + 4 <= end; j += 4) {
        int u0 = d_col[j], u1 = d_col[j + 1], u2 = d_col[j + 2], u3 = d_col[j + 3];
        float2 t0 = g2[u0 * 32 + lane];
        float2 t1 = g2[u1 * 32 + lane];
        float2 t2 = g2[u2 * 32 + lane];
        float2 t3 = g2[u3 * 32 + lane];
        acc.x += (t0.x + t1.x) + (t2.x + t3.x);
        acc.y += (t0.y + t1.y) + (t2.y + t3.y);
    }
    for (; j < end; ++j) {
        int u = d_col[j];
        float2 t = g2[u * 32 + lane];
        acc.x += t.x; acc.y += t.y;
    }
    float di = d_dinv[v];
    float oA = fmaxf(fmaf(di, acc.x, bias[lane]), 0.0f);
    float oB = fmaxf(fmaf(di, acc.y, bias[lane + 32]), 0.0f);

    unsigned iA = (unsigned)v * 64u + (unsigned)lane;   // channel lane
    bool kA = keep_elem(k0, k1, iA);
    bool kB = keep_elem(k0, k1, iA + 32u);              // channel lane+32
    const float inv_keep = 1.0f / 0.7f;
    float2 hv;
    hv.x = kA ? oA * inv_keep : 0.0f;
    hv.y = kB ? oB * inv_keep : 0.0f;
    reinterpret_cast<float2*>(d_h)[v * 32 + lane] = hv;
}

// ---------------- Mean pool per graph (batch sorted -> binary search bounds) ----------------
__global__ void k_pool(const int* __restrict__ batch) {
    __shared__ int sse[2];
    __shared__ float2 red[8][32];
    int g = blockIdx.x;
    int tid = threadIdx.x;
    if (tid < 2) {
        int target = g + tid;   // lower_bound(batch, target)
        int lo = 0, hi = N_NODES;
        while (lo < hi) { int m = (lo + hi) >> 1; if (batch[m] < target) lo = m + 1; else hi = m; }
        sse[tid] = lo;
    }
    __syncthreads();
    int start = sse[0], end = sse[1];
    int p = tid & 31, grp = tid >> 5;
    float2 acc = make_float2(0.f, 0.f);
    const float2* __restrict__ h2 = reinterpret_cast<const float2*>(d_h);
    for (int v = start + grp; v < end; v += 8) {
        float2 t = h2[v * 32 + p];
        acc.x += t.x; acc.y += t.y;
    }
    red[grp][p] = acc;
    __syncthreads();
    if (grp == 0) {
#pragma unroll
        for (int i = 1; i < 8; i++) { acc.x += red[i][p].x; acc.y += red[i][p].y; }
        float cnt = fmaxf((float)(end - start), 1.0f);
        reinterpret_cast<float2*>(d_pooled)[g * 32 + p] =
            make_float2(acc.x / cnt, acc.y / cnt);
    }
}

// ---------------- MLP head: Linear->ReLU->dropout->Linear ----------------
__global__ void k_head(const float* __restrict__ Wm1, const float* __restrict__ bm1,
                       const float* __restrict__ Wm2, const float* __restrict__ bm2,
                       float* __restrict__ out, unsigned k0, unsigned k1) {
    __shared__ float Ps[64][64];   // pooled in storage order; reused for m after sync
    __shared__ float Ws[64][64];   // Wm1 with permuted rows to match storage order
    int tid = threadIdx.x;
    for (int idx = tid; idx < 4096; idx += 1024) {
        Ps[idx >> 6][idx & 63] = d_pooled[idx];
    }
    for (int idx = tid; idx < 4096; idx += 1024) {
        int s = idx >> 6, c = idx & 63;
        int krow = (s >> 1) + ((s & 1) << 5);
        Ws[s][c] = Wm1[krow * 64 + c];
    }
    __syncthreads();

    int c = tid & 63, gb = tid >> 6;          // gb in 0..15
    float mv[2][2];                            // [halfg][0:g, 1:g+32]
#pragma unroll
    for (int halfg = 0; halfg < 2; ++halfg) {
        int g = gb + halfg * 16;
        float mA = bm1[c], mB = bm1[c];
#pragma unroll
        for (int s = 0; s < 64; s++) {
            mA = fmaf(Ps[g][s], Ws[s][c], mA);
            mB = fmaf(Ps[g + 32][s], Ws[s][c], mB);
        }
        mA = fmaxf(mA, 0.0f);
        mB = fmaxf(mB, 0.0f);
        unsigned iA = (unsigned)g * 64u + (unsigned)c;
        unsigned iB = (unsigned)(g + 32) * 64u + (unsigned)c;
        const float inv_keep = 1.0f / 0.7f;
        mv[halfg][0] = keep_elem(k0, k1, iA) ? mA * inv_keep : 0.0f;
        mv[halfg][1] = keep_elem(k0, k1, iB) ? mB * inv_keep : 0.0f;
    }
    __syncthreads();   // everyone done reading Ps
#pragma unroll
    for (int halfg = 0; halfg < 2; ++halfg) {
        int g = gb + halfg * 16;
        Ps[g][c] = mv[halfg][0];
        Ps[g + 32][c] = mv[halfg][1];
    }
    __syncthreads();
    if (tid < 64) {
        float o = bm2[0];
#pragma unroll
        for (int cc = 0; cc < 64; ++cc) o = fmaf(Ps[tid][cc], Wm2[cc], o);
        out[tid] = o;
    }
}

// ---------------- host threefry (for key splitting) ----------------
static inline void tf_host(unsigned k0, unsigned k1, unsigned c0, unsigned c1,
                           unsigned& o0, unsigned& o1) {
    unsigned ks2 = k0 ^ k1 ^ 0x1BD11BDAu;
    unsigned x0 = c0 + k0, x1 = c1 + k1;
#define HROT(x, r) (((x) << (r)) | ((x) >> (32 - (r))))
#define HRND(r) { x0 += x1; x1 = HROT(x1, r); x1 ^= x0; }
    HRND(13) HRND(15) HRND(26) HRND(6)   x0 += k1;  x1 += ks2 + 1u;
    HRND(17) HRND(29) HRND(16) HRND(24)  x0 += ks2; x1 += k0 + 2u;
    HRND(13) HRND(15) HRND(26) HRND(6)   x0 += k0;  x1 += k1 + 3u;
    HRND(17) HRND(29) HRND(16) HRND(24)  x0 += k1;  x1 += ks2 + 4u;
    HRND(13) HRND(15) HRND(26) HRND(6)   x0 += ks2; x1 += k0 + 5u;
#undef HRND
#undef HROT
    o0 = x0; o1 = x1;
}

extern "C" void kernel_launch(void* const* d_in, const int* in_sizes, int n_in,
                              void* d_out, int out_size) {
    const float* x     = (const float*)d_in[0];
    const int*   ei    = (const int*)d_in[1];
    const int*   batch = (const int*)d_in[2];
    const float* W1 = (const float*)d_in[3];  const float* b1 = (const float*)d_in[4];
    const float* W2 = (const float*)d_in[5];  const float* b2 = (const float*)d_in[6];
    const float* W3 = (const float*)d_in[7];  const float* b3 = (const float*)d_in[8];
    const float* Wm1 = (const float*)d_in[9]; const float* bm1 = (const float*)d_in[10];
    const float* Wm2 = (const float*)d_in[11];const float* bm2 = (const float*)d_in[12];
    float* out = (float*)d_out;

    // jax_threefry_partitionable=True (modern default):
    // split(key(42), 4) is fold-like: dk[i] = threefry((0,42), (0, i)) -> full (o0,o1).
    unsigned dk[4][2];
    for (unsigned i = 0; i < 4; i++)
        tf_host(0u, 42u, 0u, i, dk[i][0], dk[i][1]);

    const int NB_SCAN = (N_NODES + 1023) / 1024;   // 79

    // --- CSR build (per dst) + degrees ---
    k_zero_cnt<<<(N_NODES + 255) / 256, 256>>>();
    k_hist<<<(N_EDGES + 255) / 256, 256>>>(ei);
    k_scan1<<<NB_SCAN, 1024>>>();
    k_scan2<<<1, 32>>>(NB_SCAN);
    k_scan3<<<(N_NODES + 255) / 256, 256>>>();
    k_scatter<<<(N_EDGES + 255) / 256, 256>>>(ei);

    const int AGG_BLOCKS = (N_NODES * 32 + 255) / 256;

    // --- Layer 1 ---
    k_gemm<128, false><<<N_NODES / 64, 256>>>(x, W1);
    k_agg<<<AGG_BLOCKS, 256>>>(b1, dk[0][0], dk[0][1]);
    // --- Layer 2 ---
    k_gemm<64, true><<<N_NODES / 64, 256>>>(nullptr, W2);
    k_agg<<<AGG_BLOCKS, 256>>>(b2, dk[1][0], dk[1][1]);
    // --- Layer 3 ---
    k_gemm<64, true><<<N_NODES / 64, 256>>>(nullptr, W3);
    k_agg<<<AGG_BLOCKS, 256>>>(b3, dk[2][0], dk[2][1]);

    // --- Pool + head ---
    k_pool<<<64, 256>>>(batch);
    k_head<<<1, 1024>>>(Wm1, bm1, Wm2, bm2, out, dk[3][0], dk[3][1]);

    (void)in_sizes; (void)n_in; (void)out_size;
}